// round 15
// baseline (speedup 1.0000x reference)
#include <cuda_runtime.h>
#include <math.h>

#define F 256
#define NB 1024            // row-chunks: B=65536 -> exactly 64 rows per chunk

// Stage-1 partials, transposed: [F][NB] float4 = 4 MB
__device__ float4 g_part[F * NB];
__device__ double g_bits[F];
__device__ int    g_ticket;          // zero-initialized; reset by last block

__device__ __forceinline__ float fast_lg2(float a) {
    float r; asm("lg2.approx.f32 %0, %1;" : "=f"(r) : "f"(a)); return r;
}
__device__ __forceinline__ float fast_ex2(float a) {
    float r; asm("ex2.approx.f32 %0, %1;" : "=f"(r) : "f"(a)); return r;
}

// 128-thread CTAs: grid = NB*2. CTA covers 64 rows x 128 features.
//   chunk = blockIdx.x >> 1,  f = (blockIdx.x & 1)*128 + tid     (R11 geometry)
template<int ROWS>
__global__ void __launch_bounds__(128) mdl_pass1(
    const float* __restrict__ res,
    const float* __restrict__ lambda1,
    const float* __restrict__ lambda2,
    int rows_rt)
{
    const int chunk = blockIdx.x >> 1;
    const int f = ((blockIdx.x & 1) << 7) + threadIdx.x;   // feature 0..255
    const float l1 = lambda1[f];
    const float l2 = lambda2[f];
    // clamp lambdas away from 0 (tiny case flows through the same path)
    float lamP = (fabsf(l1) < 1e-8f) ? 1e-8f : l1;
    float lamN = 2.0f - l2;
    if (fabsf(lamN) < 1e-8f) lamN = 1e-8f;
    const float rlamP  =  1.0f / lamP;
    const float nrlamN = -1.0f / lamN;
    // single-interval safety: safe == (loB < x <= hiB); bad-lambda flags folded in
    const float hiB = (fabsf(l1) <= 1.9f) ? 1000.0f : -0.0f;
    const float loB = (fabsf(l2) <= 1.9f) ? -0.99f  :  0.0f;

    const int rows = (ROWS > 0) ? ROWS : rows_rt;
    const float* p = res + (size_t)chunk * rows * F + f;

    float cnt = 0.0f, sy = 0.0f, sy2 = 0.0f, slj2 = 0.0f;

#pragma unroll 8
    for (int r = 0; r < rows; ++r) {
        const float x = __ldcs(p + r * F);       // LDG [base+imm]
        const bool pos = (x >= 0.0f);

        // pos clip at 1000 dropped (those elements are masked -> exact);
        // neg clamp at -0.989 kept (affects the safe band (-0.99,-0.989]).
        const float a  = 1.0f + fabsf(fmaxf(x, -0.989f));
        const float t2 = fast_lg2(a);                    // log2(1+|x|clip)
        const float lam = pos ? lamP : lamN;
        const float u2  = lam * t2;
        const float ee  = fast_ex2(u2);
        const float rl  = pos ? rlamP : nrlamN;          // sign folded in
        const float y   = fmaf(ee, rl, -rl);             // (2^u2 - 1) * rl

        const bool safe = (x > loB) && (x <= hiB);
        if (safe) {
            cnt  += 1.0f;
            sy   += y;
            sy2   = fmaf(y, y, sy2);
            slj2 += (u2 - t2);                           // log_jac / ln2
        }
    }

    g_part[f * NB + chunk] = make_float4(cnt, sy, sy2, slj2);   // one STG.128
}

// Fused tail: 256 blocks x 256 threads; block = one feature.
// 8 warps reduce the feature's NB float4 slots (coalesced LDG.128), shuffle +
// smem combine, thread 0 does the double-precision bit math -> g_bits[f].
// The last block (ticket) re-reduces all 256 bits -> out[0], resets ticket.
__global__ __launch_bounds__(256) void mdl_pass2(
    const float* __restrict__ resolutions,
    float* __restrict__ out, int B)
{
    const int gf   = blockIdx.x;
    const int w    = threadIdx.x >> 5;
    const int lane = threadIdx.x & 31;

    const float4* b0 = g_part + (size_t)gf * NB;
    double cnt = 0.0, sy = 0.0, sy2 = 0.0, slj = 0.0;
#pragma unroll 4
    for (int b = threadIdx.x; b < NB; b += 256) {        // fully coalesced
        const float4 v = b0[b];
        cnt += (double)v.x; sy += (double)v.y;
        sy2 += (double)v.z; slj += (double)v.w;
    }
#pragma unroll
    for (int o = 16; o > 0; o >>= 1) {
        cnt += __shfl_down_sync(0xffffffffu, cnt, o);
        sy  += __shfl_down_sync(0xffffffffu, sy,  o);
        sy2 += __shfl_down_sync(0xffffffffu, sy2, o);
        slj += __shfl_down_sync(0xffffffffu, slj, o);
    }

    __shared__ double sh[8][4];
    if (lane == 0) { sh[w][0] = cnt; sh[w][1] = sy; sh[w][2] = sy2; sh[w][3] = slj; }
    __syncthreads();

    __shared__ int s_last;
    if (threadIdx.x == 0) {
        cnt = 0; sy = 0; sy2 = 0; slj = 0;
#pragma unroll
        for (int i = 0; i < 8; ++i) {
            cnt += sh[i][0]; sy += sh[i][1]; sy2 += sh[i][2]; slj += sh[i][3];
        }

        const double LN2 = 0.6931471805599453;
        const double LOG2_2PIE = 2.0470955851806783;

        const double Bd    = (double)B;
        const double nf    = cnt;
        const double nexc  = Bd - nf;
        const double denom = fmax(nf, 1.0);
        const double mean  = sy / denom;
        double var = (sy2 - 2.0 * mean * sy + mean * mean * nf) / denom;
        var = fmax(var, 1e-12);

        const double diff_bits = (nf > 1.0) ? nf * (LOG2_2PIE + 0.5 * log2(var)) : 0.0;
        const double jac_bits  = slj;        // accumulated in log2 units
        const double rres      = (double)resolutions[gf];
        const double exc_bits  = (nexc > 0.0) ? nexc * (-log2(rres)) : 0.0;
        const double log_binom = lgamma(Bd + 1.0) - lgamma(nexc + 1.0)
                               - lgamma(Bd - nexc + 1.0);
        const double part_bits = (nexc > 0.0 && nexc < Bd) ? (log_binom / LN2) : 0.0;
        const double lambda_bits = 2.0 * (log(100.0) / LN2);

        g_bits[gf] = diff_bits + jac_bits + exc_bits + part_bits + lambda_bits;

        __threadfence();                                  // publish g_bits[gf]
        const int t = atomicAdd(&g_ticket, 1);
        s_last = (t == F - 1) ? 1 : 0;
    }
    __syncthreads();

    if (s_last) {
        __threadfence();                                  // acquire all g_bits
        __shared__ double sb[F];
        sb[threadIdx.x] = g_bits[threadIdx.x];
        __syncthreads();
#pragma unroll
        for (int s = 128; s > 0; s >>= 1) {
            if (threadIdx.x < s) sb[threadIdx.x] += sb[threadIdx.x + s];
            __syncthreads();
        }
        if (threadIdx.x == 0) {
            out[0] = (float)sb[0];
            g_ticket = 0;                                 // reset for next replay
        }
    }
}

extern "C" void kernel_launch(void* const* d_in, const int* in_sizes, int n_in,
                              void* d_out, int out_size)
{
    const float* residuals   = (const float*)d_in[0];
    const float* lambda1     = (const float*)d_in[1];
    const float* lambda2     = (const float*)d_in[2];
    const float* resolutions = (const float*)d_in[3];
    float* out = (float*)d_out;

    const int B = in_sizes[0] / F;

    if (B == NB * 64) {
        mdl_pass1<64><<<NB * 2, 128>>>(residuals, lambda1, lambda2, 64);
    } else {
        const int rows = (B + NB - 1) / NB;   // assumes B % NB == 0
        mdl_pass1<0><<<NB * 2, 128>>>(residuals, lambda1, lambda2, rows);
    }
    mdl_pass2<<<F, 256>>>(resolutions, out, B);
}